// round 1
// baseline (speedup 1.0000x reference)
#include <cuda_runtime.h>
#include <cuda_bf16.h>
#include <math.h>

#define B_  2
#define L_  2048
#define S_  2048
#define D_  256
#define H_  8
#define HD_ 32

// ---------------- scratch (__device__ globals; no runtime alloc) ----------------
__device__ float g_Q[(size_t)B_ * L_ * D_];
__device__ float g_K[(size_t)B_ * S_ * D_];
__device__ float g_V[(size_t)B_ * S_ * D_];
__device__ float g_A[(size_t)B_ * H_ * L_ * S_];   // 256 MB scores
__device__ float g_O[(size_t)B_ * L_ * D_];
__device__ float g_M[(size_t)B_ * L_ * D_];
__device__ float g_CAT[(size_t)B_ * L_ * 2 * D_];
__device__ float g_HB[(size_t)B_ * L_ * 2 * D_];

// ---------------- generic NT GEMM: Y[M,N] = X[M,K] @ W[N,K]^T ----------------
// BM=BN=64, BK=16, 256 threads, 4x4 microtile. M%64==0, N%64==0, K%16==0.
template <bool RELU>
__global__ void gemm_nt(const float* __restrict__ X, const float* __restrict__ W,
                        float* __restrict__ Y, int M, int N, int K) {
    __shared__ float Xs[64][17];
    __shared__ float Ws[64][17];
    const int bm = blockIdx.y * 64;
    const int bn = blockIdx.x * 64;
    const int tid = threadIdx.x;
    const int ty = tid >> 4, tx = tid & 15;
    float acc[4][4] = {};
    for (int k0 = 0; k0 < K; k0 += 16) {
        #pragma unroll
        for (int i = tid; i < 64 * 16; i += 256) {
            int r = i >> 4, c = i & 15;
            Xs[r][c] = X[(size_t)(bm + r) * K + k0 + c];
            Ws[r][c] = W[(size_t)(bn + r) * K + k0 + c];
        }
        __syncthreads();
        #pragma unroll
        for (int kk = 0; kk < 16; kk++) {
            float a[4], b[4];
            #pragma unroll
            for (int i = 0; i < 4; i++) a[i] = Xs[ty * 4 + i][kk];
            #pragma unroll
            for (int j = 0; j < 4; j++) b[j] = Ws[tx * 4 + j][kk];
            #pragma unroll
            for (int i = 0; i < 4; i++)
                #pragma unroll
                for (int j = 0; j < 4; j++) acc[i][j] += a[i] * b[j];
        }
        __syncthreads();
    }
    #pragma unroll
    for (int i = 0; i < 4; i++)
        #pragma unroll
        for (int j = 0; j < 4; j++) {
            float v = acc[i][j];
            if (RELU) v = fmaxf(v, 0.0f);
            Y[(size_t)(bm + ty * 4 + i) * N + bn + tx * 4 + j] = v;
        }
}

// ---------------- QK^T * scale * attn_factor -> A[bh, l, s] ----------------
// grid: (S/64, L/64, B*H), 256 threads, 4x4 microtile over 64x64, K=32 full.
__global__ void qk_kernel(const float* __restrict__ Q, const float* __restrict__ Kp,
                          const float* __restrict__ af, float* __restrict__ A) {
    __shared__ float Qs[64][33];
    __shared__ float Ks[64][33];
    const int bh = blockIdx.z;
    const int b = bh / H_, h = bh % H_;
    const int l0 = blockIdx.y * 64, s0 = blockIdx.x * 64;
    const float* Qb = Q + (size_t)b * L_ * D_ + h * HD_;
    const float* Kb = Kp + (size_t)b * S_ * D_ + h * HD_;
    const int tid = threadIdx.x;
    #pragma unroll
    for (int i = tid; i < 64 * 32; i += 256) {
        int r = i >> 5, c = i & 31;
        Qs[r][c] = Qb[(size_t)(l0 + r) * D_ + c];
        Ks[r][c] = Kb[(size_t)(s0 + r) * D_ + c];
    }
    __syncthreads();
    const int ty = tid >> 4, tx = tid & 15;
    float acc[4][4] = {};
    #pragma unroll
    for (int kk = 0; kk < 32; kk++) {
        float a[4], b2[4];
        #pragma unroll
        for (int i = 0; i < 4; i++) a[i] = Qs[ty * 4 + i][kk];
        #pragma unroll
        for (int j = 0; j < 4; j++) b2[j] = Ks[tx * 4 + j][kk];
        #pragma unroll
        for (int i = 0; i < 4; i++)
            #pragma unroll
            for (int j = 0; j < 4; j++) acc[i][j] += a[i] * b2[j];
    }
    const float scale = 0.1767766952966369f;  // 1/sqrt(32)
    #pragma unroll
    for (int i = 0; i < 4; i++) {
        int l = l0 + ty * 4 + i;
        #pragma unroll
        for (int j = 0; j < 4; j++) {
            int s = s0 + tx * 4 + j;
            float f = af[((size_t)b * L_ + l) * S_ + s];
            A[((size_t)bh * L_ + l) * S_ + s] = acc[i][j] * scale * f;
        }
    }
}

// ---------------- softmax over last dim (S=2048), one block per row ----------------
__global__ void softmax_kernel(float* __restrict__ A) {
    const size_t row = blockIdx.x;
    float* p = A + row * (size_t)S_;
    const int tid = threadIdx.x;
    float v[8];
    float m = -1e30f;
    #pragma unroll
    for (int i = 0; i < 8; i++) { v[i] = p[tid + i * 256]; m = fmaxf(m, v[i]); }
    __shared__ float red[256];
    red[tid] = m; __syncthreads();
    #pragma unroll
    for (int off = 128; off > 0; off >>= 1) {
        if (tid < off) red[tid] = fmaxf(red[tid], red[tid + off]);
        __syncthreads();
    }
    m = red[0]; __syncthreads();
    float s = 0.0f;
    #pragma unroll
    for (int i = 0; i < 8; i++) { v[i] = __expf(v[i] - m); s += v[i]; }
    red[tid] = s; __syncthreads();
    #pragma unroll
    for (int off = 128; off > 0; off >>= 1) {
        if (tid < off) red[tid] += red[tid + off];
        __syncthreads();
    }
    const float inv = 1.0f / red[0];
    #pragma unroll
    for (int i = 0; i < 8; i++) p[tid + i * 256] = v[i] * inv;
}

// ---------------- O[b,l,h*32+d] = sum_s A[bh,l,s] * V[b,s,h*32+d] ----------------
// grid: (L/64, 1, B*H), block (32,8). Each thread: 8 rows, 1 col.
__global__ void av_kernel(const float* __restrict__ A, const float* __restrict__ V,
                          float* __restrict__ O) {
    __shared__ float As[64][33];
    __shared__ float Vs[32][33];
    const int bh = blockIdx.z;
    const int b = bh / H_, h = bh % H_;
    const int l0 = blockIdx.x * 64;
    const float* Ab = A + ((size_t)bh * L_ + l0) * S_;
    const float* Vb = V + (size_t)b * S_ * D_ + h * HD_;
    const int tx = threadIdx.x, ty = threadIdx.y;
    const int tid = ty * 32 + tx;
    float acc[8] = {};
    for (int s0 = 0; s0 < S_; s0 += 32) {
        #pragma unroll
        for (int i = tid; i < 64 * 32; i += 256) {
            int r = i >> 5, c = i & 31;
            As[r][c] = Ab[(size_t)r * S_ + s0 + c];
        }
        {
            int r = tid >> 5, c = tid & 31;  // 256 threads cover 32x32 exactly... (8 rows)
            #pragma unroll
            for (int rr = r; rr < 32; rr += 8) Vs[rr][c] = Vb[(size_t)(s0 + rr) * D_ + c];
        }
        __syncthreads();
        #pragma unroll
        for (int kk = 0; kk < 32; kk++) {
            float bv = Vs[kk][tx];
            #pragma unroll
            for (int i = 0; i < 8; i++) acc[i] += As[ty + i * 8][kk] * bv;
        }
        __syncthreads();
    }
    #pragma unroll
    for (int i = 0; i < 8; i++)
        O[((size_t)b * L_ + l0 + ty + i * 8) * D_ + h * HD_ + tx] = acc[i];
}

// ---------------- LayerNorm over D=256, one block (256 thr) per row ----------------
template <bool RESID>
__global__ void ln_kernel(const float* __restrict__ in, const float* __restrict__ g,
                          const float* __restrict__ bt, const float* __restrict__ resid,
                          float* __restrict__ out) {
    const size_t row = blockIdx.x;
    const int tid = threadIdx.x;
    float x = in[row * D_ + tid];
    __shared__ float red[256];
    red[tid] = x; __syncthreads();
    #pragma unroll
    for (int off = 128; off > 0; off >>= 1) {
        if (tid < off) red[tid] += red[tid + off];
        __syncthreads();
    }
    const float mean = red[0] * (1.0f / D_);
    __syncthreads();
    const float d = x - mean;
    red[tid] = d * d; __syncthreads();
    #pragma unroll
    for (int off = 128; off > 0; off >>= 1) {
        if (tid < off) red[tid] += red[tid + off];
        __syncthreads();
    }
    const float var = red[0] * (1.0f / D_);
    float y = d * rsqrtf(var + 1e-5f) * g[tid] + bt[tid];
    if (RESID) y += resid[row * D_ + tid];
    out[row * D_ + tid] = y;
}

// ---------------- concat [x, m] -> cat[row, 512] ----------------
__global__ void concat_kernel(const float* __restrict__ x, const float* __restrict__ m,
                              float* __restrict__ cat) {
    size_t i = (size_t)blockIdx.x * 256 + threadIdx.x;
    size_t row = i >> 9;       // /512
    int c = (int)(i & 511);
    cat[i] = (c < 256) ? x[row * 256 + c] : m[row * 256 + (c - 256)];
}

// ---------------- launch ----------------
extern "C" void kernel_launch(void* const* d_in, const int* in_sizes, int n_in,
                              void* d_out, int out_size) {
    const float* x   = (const float*)d_in[0];
    const float* src = (const float*)d_in[1];
    const float* af  = (const float*)d_in[2];
    const float* Wq  = (const float*)d_in[3];
    const float* Wk  = (const float*)d_in[4];
    const float* Wv  = (const float*)d_in[5];
    const float* Wm  = (const float*)d_in[6];
    const float* W1  = (const float*)d_in[7];
    const float* W2  = (const float*)d_in[8];
    const float* g1  = (const float*)d_in[9];
    const float* b1  = (const float*)d_in[10];
    const float* g2  = (const float*)d_in[11];
    const float* b2  = (const float*)d_in[12];
    float* out = (float*)d_out;

    float *Q, *K, *V, *A, *O, *M, *CAT, *HB;
    cudaGetSymbolAddress((void**)&Q, g_Q);
    cudaGetSymbolAddress((void**)&K, g_K);
    cudaGetSymbolAddress((void**)&V, g_V);
    cudaGetSymbolAddress((void**)&A, g_A);
    cudaGetSymbolAddress((void**)&O, g_O);
    cudaGetSymbolAddress((void**)&M, g_M);
    cudaGetSymbolAddress((void**)&CAT, g_CAT);
    cudaGetSymbolAddress((void**)&HB, g_HB);

    const int ML = B_ * L_;  // 4096
    const int MS = B_ * S_;  // 4096

    // projections
    gemm_nt<false><<<dim3(D_ / 64, ML / 64), 256>>>(x,   Wq, Q, ML, D_, D_);
    gemm_nt<false><<<dim3(D_ / 64, MS / 64), 256>>>(src, Wk, K, MS, D_, D_);
    gemm_nt<false><<<dim3(D_ / 64, MS / 64), 256>>>(src, Wv, V, MS, D_, D_);

    // attention
    qk_kernel<<<dim3(S_ / 64, L_ / 64, B_ * H_), 256>>>(Q, K, af, A);
    softmax_kernel<<<B_ * H_ * L_, 256>>>(A);
    av_kernel<<<dim3(L_ / 64, 1, B_ * H_), dim3(32, 8)>>>(A, V, O);

    // output proj + LN1
    gemm_nt<false><<<dim3(D_ / 64, ML / 64), 256>>>(O, Wm, M, ML, D_, D_);
    ln_kernel<false><<<ML, 256>>>(M, g1, b1, nullptr, M);

    // MLP
    concat_kernel<<<(ML * 512) / 256, 256>>>(x, M, CAT);
    gemm_nt<true><<<dim3(512 / 64, ML / 64), 256>>>(CAT, W1, HB, ML, 512, 512);
    gemm_nt<false><<<dim3(D_ / 64, ML / 64), 256>>>(HB, W2, Q, ML, D_, 512);  // reuse Q

    // LN2 + residual -> out
    ln_kernel<true><<<ML, 256>>>(Q, g2, b2, x, out);
}

// round 2
// speedup vs baseline: 1.3674x; 1.3674x over previous
#include <cuda_runtime.h>
#include <math.h>

typedef unsigned long long ull;
typedef unsigned int uint32;

#define B_  2
#define L_  2048
#define S_  2048
#define D_  256
#define H_  8
#define HD_ 32
#define LT  16
#define ST  32

// ---------------- f32x2 packed math (sm_103a FFMA2 path) ----------------
#define PACK2(d, x, y) asm("mov.b64 %0, {%1, %2};" : "=l"(d) : "r"(__float_as_uint(x)), "r"(__float_as_uint(y)))
#define UNPACK2(x, y, d) do { uint32 _lo, _hi; \
    asm("mov.b64 {%0, %1}, %2;" : "=r"(_lo), "=r"(_hi) : "l"(d)); \
    (x) = __uint_as_float(_lo); (y) = __uint_as_float(_hi); } while (0)
#define FMA2(d, a, b, c) asm("fma.rn.f32x2 %0, %1, %2, %3;" : "=l"(d) : "l"(a), "l"(b), "l"(c))
#define MUL2(d, a, b)    asm("mul.rn.f32x2 %0, %1, %2;"     : "=l"(d) : "l"(a), "l"(b))

// ---------------- scratch ----------------
__device__ float g_Q[(size_t)B_ * L_ * D_];
__device__ float g_K[(size_t)B_ * S_ * D_];
__device__ float g_V[(size_t)B_ * S_ * D_];
__device__ float g_O[(size_t)B_ * L_ * D_];
__device__ float g_M[(size_t)B_ * L_ * D_];
__device__ float g_HB[(size_t)B_ * L_ * 2 * D_];
__device__ float g_T[(size_t)B_ * L_ * D_];

// ---------------- generic NT GEMM: Y[M,N] = X[M,K] @ W[N,K]^T ----------------
// SPLIT: X is [x | X2] concatenated along K (each of width 256), K=512.
template <bool RELU, bool SPLIT>
__global__ void gemm_nt(const float* __restrict__ X, const float* __restrict__ X2,
                        const float* __restrict__ W, float* __restrict__ Y,
                        int M, int N, int K) {
    __shared__ float Xs[64][17];
    __shared__ float Ws[64][17];
    const int bm = blockIdx.y * 64;
    const int bn = blockIdx.x * 64;
    const int tid = threadIdx.x;
    const int ty = tid >> 4, tx = tid & 15;
    float acc[4][4] = {};
    for (int k0 = 0; k0 < K; k0 += 16) {
        #pragma unroll
        for (int i = tid; i < 64 * 16; i += 256) {
            int r = i >> 4, c = i & 15;
            int kc = k0 + c;
            float xv;
            if (SPLIT) {
                xv = (kc < 256) ? X[(size_t)(bm + r) * 256 + kc]
                                : X2[(size_t)(bm + r) * 256 + (kc - 256)];
            } else {
                xv = X[(size_t)(bm + r) * K + kc];
            }
            Xs[r][c] = xv;
            Ws[r][c] = W[(size_t)(bn + r) * K + kc];
        }
        __syncthreads();
        #pragma unroll
        for (int kk = 0; kk < 16; kk++) {
            float a[4], b[4];
            #pragma unroll
            for (int i = 0; i < 4; i++) a[i] = Xs[ty * 4 + i][kk];
            #pragma unroll
            for (int j = 0; j < 4; j++) b[j] = Ws[tx * 4 + j][kk];
            #pragma unroll
            for (int i = 0; i < 4; i++)
                #pragma unroll
                for (int j = 0; j < 4; j++) acc[i][j] += a[i] * b[j];
        }
        __syncthreads();
    }
    #pragma unroll
    for (int i = 0; i < 4; i++)
        #pragma unroll
        for (int j = 0; j < 4; j++) {
            float v = acc[i][j];
            if (RELU) v = fmaxf(v, 0.0f);
            Y[(size_t)(bm + ty * 4 + i) * N + bn + tx * 4 + j] = v;
        }
}

// ---------------- fused flash attention ----------------
// Block: 256 threads = 8 warps, warp h handles head h. Tile: LT=16 rows (l),
// S-loop in tiles of ST=32. Online softmax with attn_factor folded pre-softmax.
// Smem layout (floats):
//   Qt [256][20]   (k-major, padded 20, float4 over l)       off 0      size 5120
//   Kt [256][33]   (k-major, padded 33, scalar, conflict-free) off 5120  size 8448
//   Vs [32][260]   (natural, float4 over d)                  off 13568  size 8320
//   Pt [8][32][20] (per-head p tile, [s][l], float4 over l)  off 21888  size 5120
//   Af [16][36]    (attn_factor tile, float4 over s)         off 27008  size 576
#define SMEM_FLOATS 27584
#define SMEM_BYTES  (SMEM_FLOATS * 4)

__global__ void __launch_bounds__(256, 2) attn_fused(
    const float* __restrict__ Qg, const float* __restrict__ Kg,
    const float* __restrict__ Vg, const float* __restrict__ af,
    float* __restrict__ Og) {
    extern __shared__ float sm[];
    float* Qt = sm;
    float* Kt = sm + 5120;
    float* Vs = sm + 13568;
    float* Pt = sm + 21888;
    float* Af = sm + 27008;

    const int b = blockIdx.y;
    const int l0 = blockIdx.x * LT;
    const int tid = threadIdx.x;
    const int wid = tid >> 5;      // head
    const int lane = tid & 31;
    const int lg = lane & 3;       // l-group: rows l = lg*4 + i
    const int sg = lane >> 2;      // s-group (QK) / d-group (AV)

    // load Q tile transposed: Qt[k][l] = Q[b, l0+l, k]
    for (int i = tid; i < LT * D_; i += 256) {
        int l = i >> 8, k = i & 255;
        Qt[k * 20 + l] = Qg[((size_t)b * L_ + l0 + l) * D_ + k];
    }

    float m[4], ssum[4];
    #pragma unroll
    for (int i = 0; i < 4; i++) { m[i] = -1e30f; ssum[i] = 0.0f; }
    ull zero; PACK2(zero, 0.0f, 0.0f);
    ull oacc[2][4];
    #pragma unroll
    for (int p = 0; p < 2; p++)
        #pragma unroll
        for (int d = 0; d < 4; d++) oacc[p][d] = zero;

    float* PtW = Pt + wid * (ST * 20);
    const float* Kb  = Kg + (size_t)b * S_ * D_;
    const float* Vb  = Vg + (size_t)b * S_ * D_;
    const float* afb = af + ((size_t)b * L_ + l0) * S_;
    const float SCALE = 0.1767766952966369f;  // 1/sqrt(32)

    for (int s0 = 0; s0 < S_; s0 += ST) {
        __syncthreads();
        // K tile transposed: Kt[k][s]
        for (int i = tid; i < ST * D_; i += 256) {
            int s = i >> 8, k = i & 255;
            Kt[k * 33 + s] = Kb[(size_t)(s0 + s) * D_ + k];
        }
        // V tile natural (vectorized)
        for (int i = tid; i < ST * (D_ / 4); i += 256) {
            int s = i >> 6, k4 = (i & 63) << 2;
            *(float4*)&Vs[s * 260 + k4] = *(const float4*)&Vb[(size_t)(s0 + s) * D_ + k4];
        }
        // attn_factor tile
        for (int i = tid; i < LT * ST; i += 256) {
            int l = i >> 5, s = i & 31;
            Af[l * 36 + s] = afb[(size_t)l * S_ + s0 + s];
        }
        __syncthreads();

        // ---- QK^T (16l x 32s per warp), f32x2 paired over s ----
        ull sacc[4][2];
        #pragma unroll
        for (int i = 0; i < 4; i++) { sacc[i][0] = zero; sacc[i][1] = zero; }
        const float* QtH = Qt + (wid * HD_) * 20 + lg * 4;
        const float* KtH = Kt + (wid * HD_) * 33 + sg * 4;
        #pragma unroll
        for (int k = 0; k < HD_; k++) {
            float4 a4 = *(const float4*)&QtH[k * 20];
            float b0 = KtH[k * 33 + 0];
            float b1 = KtH[k * 33 + 1];
            float b2 = KtH[k * 33 + 2];
            float b3 = KtH[k * 33 + 3];
            ull bp0, bp1; PACK2(bp0, b0, b1); PACK2(bp1, b2, b3);
            ull a0, a1, a2, a3;
            PACK2(a0, a4.x, a4.x); PACK2(a1, a4.y, a4.y);
            PACK2(a2, a4.z, a4.z); PACK2(a3, a4.w, a4.w);
            FMA2(sacc[0][0], a0, bp0, sacc[0][0]); FMA2(sacc[0][1], a0, bp1, sacc[0][1]);
            FMA2(sacc[1][0], a1, bp0, sacc[1][0]); FMA2(sacc[1][1], a1, bp1, sacc[1][1]);
            FMA2(sacc[2][0], a2, bp0, sacc[2][0]); FMA2(sacc[2][1], a2, bp1, sacc[2][1]);
            FMA2(sacc[3][0], a3, bp0, sacc[3][0]); FMA2(sacc[3][1], a3, bp1, sacc[3][1]);
        }

        // ---- scale * attn_factor, online softmax ----
        float sc[4][4];
        #pragma unroll
        for (int i = 0; i < 4; i++) {
            float4 afv = *(const float4*)&Af[(lg * 4 + i) * 36 + sg * 4];
            float x0, x1, x2, x3;
            UNPACK2(x0, x1, sacc[i][0]);
            UNPACK2(x2, x3, sacc[i][1]);
            sc[i][0] = x0 * (SCALE * afv.x);
            sc[i][1] = x1 * (SCALE * afv.y);
            sc[i][2] = x2 * (SCALE * afv.z);
            sc[i][3] = x3 * (SCALE * afv.w);
        }
        float tmax[4];
        #pragma unroll
        for (int i = 0; i < 4; i++)
            tmax[i] = fmaxf(fmaxf(sc[i][0], sc[i][1]), fmaxf(sc[i][2], sc[i][3]));
        #pragma unroll
        for (int off = 4; off < 32; off <<= 1)
            #pragma unroll
            for (int i = 0; i < 4; i++)
                tmax[i] = fmaxf(tmax[i], __shfl_xor_sync(0xffffffffu, tmax[i], off));
        float alpha[4], rs[4];
        #pragma unroll
        for (int i = 0; i < 4; i++) {
            float mn = fmaxf(m[i], tmax[i]);
            alpha[i] = __expf(m[i] - mn);
            m[i] = mn;
        }
        #pragma unroll
        for (int i = 0; i < 4; i++) {
            rs[i] = 0.0f;
            #pragma unroll
            for (int j = 0; j < 4; j++) {
                float p = __expf(sc[i][j] - m[i]);
                sc[i][j] = p;
                rs[i] += p;
            }
        }
        #pragma unroll
        for (int off = 4; off < 32; off <<= 1)
            #pragma unroll
            for (int i = 0; i < 4; i++)
                rs[i] += __shfl_xor_sync(0xffffffffu, rs[i], off);
        #pragma unroll
        for (int i = 0; i < 4; i++) ssum[i] = ssum[i] * alpha[i] + rs[i];

        // rescale O accumulators (paired over l)
        ull al01, al23;
        PACK2(al01, alpha[0], alpha[1]);
        PACK2(al23, alpha[2], alpha[3]);
        #pragma unroll
        for (int d = 0; d < 4; d++) {
            MUL2(oacc[0][d], oacc[0][d], al01);
            MUL2(oacc[1][d], oacc[1][d], al23);
        }

        // write P tile [s][l] (per-warp private)
        #pragma unroll
        for (int j = 0; j < 4; j++) {
            float4 v;
            v.x = sc[0][j]; v.y = sc[1][j]; v.z = sc[2][j]; v.w = sc[3][j];
            *(float4*)&PtW[(sg * 4 + j) * 20 + lg * 4] = v;
        }
        __syncwarp();

        // ---- AV: O[l][d] += p[l][s] * V[s][d], f32x2 paired over l ----
        const float* VsH = Vs + wid * HD_ + sg * 4;
        #pragma unroll
        for (int s = 0; s < ST; s++) {
            float4 p4 = *(const float4*)&PtW[s * 20 + lg * 4];
            float4 v4 = *(const float4*)&VsH[s * 260];
            ull p01, p23; PACK2(p01, p4.x, p4.y); PACK2(p23, p4.z, p4.w);
            ull vd;
            PACK2(vd, v4.x, v4.x);
            FMA2(oacc[0][0], p01, vd, oacc[0][0]); FMA2(oacc[1][0], p23, vd, oacc[1][0]);
            PACK2(vd, v4.y, v4.y);
            FMA2(oacc[0][1], p01, vd, oacc[0][1]); FMA2(oacc[1][1], p23, vd, oacc[1][1]);
            PACK2(vd, v4.z, v4.z);
            FMA2(oacc[0][2], p01, vd, oacc[0][2]); FMA2(oacc[1][2], p23, vd, oacc[1][2]);
            PACK2(vd, v4.w, v4.w);
            FMA2(oacc[0][3], p01, vd, oacc[0][3]); FMA2(oacc[1][3], p23, vd, oacc[1][3]);
        }
    }

    // finalize: divide by softmax sum, write O
    float inv[4];
    #pragma unroll
    for (int i = 0; i < 4; i++) inv[i] = 1.0f / ssum[i];
    float o[4][4];
    #pragma unroll
    for (int p = 0; p < 2; p++)
        #pragma unroll
        for (int d = 0; d < 4; d++)
            UNPACK2(o[2 * p][d], o[2 * p + 1][d], oacc[p][d]);
    #pragma unroll
    for (int i = 0; i < 4; i++) {
        float4 w;
        w.x = o[i][0] * inv[i]; w.y = o[i][1] * inv[i];
        w.z = o[i][2] * inv[i]; w.w = o[i][3] * inv[i];
        *(float4*)&Og[((size_t)b * L_ + l0 + lg * 4 + i) * D_ + wid * HD_ + sg * 4] = w;
    }
}

// ---------------- LayerNorm over D=256, one block (256 thr) per row ----------------
template <bool RESID>
__global__ void ln_kernel(const float* __restrict__ in, const float* __restrict__ g,
                          const float* __restrict__ bt, const float* __restrict__ resid,
                          float* __restrict__ out) {
    const size_t row = blockIdx.x;
    const int tid = threadIdx.x;
    float x = in[row * D_ + tid];
    __shared__ float red[256];
    red[tid] = x; __syncthreads();
    #pragma unroll
    for (int off = 128; off > 0; off >>= 1) {
        if (tid < off) red[tid] += red[tid + off];
        __syncthreads();
    }
    const float mean = red[0] * (1.0f / D_);
    __syncthreads();
    const float d = x - mean;
    red[tid] = d * d; __syncthreads();
    #pragma unroll
    for (int off = 128; off > 0; off >>= 1) {
        if (tid < off) red[tid] += red[tid + off];
        __syncthreads();
    }
    const float var = red[0] * (1.0f / D_);
    float y = d * rsqrtf(var + 1e-5f) * g[tid] + bt[tid];
    if (RESID) y += resid[row * D_ + tid];
    out[row * D_ + tid] = y;
}

// ---------------- launch ----------------
extern "C" void kernel_launch(void* const* d_in, const int* in_sizes, int n_in,
                              void* d_out, int out_size) {
    const float* x   = (const float*)d_in[0];
    const float* src = (const float*)d_in[1];
    const float* af  = (const float*)d_in[2];
    const float* Wq  = (const float*)d_in[3];
    const float* Wk  = (const float*)d_in[4];
    const float* Wv  = (const float*)d_in[5];
    const float* Wm  = (const float*)d_in[6];
    const float* W1  = (const float*)d_in[7];
    const float* W2  = (const float*)d_in[8];
    const float* g1  = (const float*)d_in[9];
    const float* b1  = (const float*)d_in[10];
    const float* g2  = (const float*)d_in[11];
    const float* b2  = (const float*)d_in[12];
    float* out = (float*)d_out;

    float *Q, *K, *V, *O, *M, *HB, *T;
    cudaGetSymbolAddress((void**)&Q, g_Q);
    cudaGetSymbolAddress((void**)&K, g_K);
    cudaGetSymbolAddress((void**)&V, g_V);
    cudaGetSymbolAddress((void**)&O, g_O);
    cudaGetSymbolAddress((void**)&M, g_M);
    cudaGetSymbolAddress((void**)&HB, g_HB);
    cudaGetSymbolAddress((void**)&T, g_T);

    cudaFuncSetAttribute(attn_fused, cudaFuncAttributeMaxDynamicSharedMemorySize, SMEM_BYTES);

    const int ML = B_ * L_;  // 4096
    const int MS = B_ * S_;  // 4096

    // projections
    gemm_nt<false, false><<<dim3(D_ / 64, ML / 64), 256>>>(x,   nullptr, Wq, Q, ML, D_, D_);
    gemm_nt<false, false><<<dim3(D_ / 64, MS / 64), 256>>>(src, nullptr, Wk, K, MS, D_, D_);
    gemm_nt<false, false><<<dim3(D_ / 64, MS / 64), 256>>>(src, nullptr, Wv, V, MS, D_, D_);

    // fused attention -> O
    attn_fused<<<dim3(L_ / LT, B_), 256, SMEM_BYTES>>>(Q, K, V, af, O);

    // output proj + LN1
    gemm_nt<false, false><<<dim3(D_ / 64, ML / 64), 256>>>(O, nullptr, Wm, M, ML, D_, D_);
    ln_kernel<false><<<ML, 256>>>(M, g1, b1, nullptr, M);

    // MLP: h = relu([x, M] @ W1^T); out_pre = h @ W2^T
    gemm_nt<true, true><<<dim3(512 / 64, ML / 64), 256>>>(x, M, W1, HB, ML, 512, 512);
    gemm_nt<false, false><<<dim3(D_ / 64, ML / 64), 256>>>(HB, nullptr, W2, T, ML, D_, 512);

    // LN2 + residual -> out
    ln_kernel<true><<<ML, 256>>>(T, g2, b2, x, out);
}

// round 4
// speedup vs baseline: 1.8035x; 1.3189x over previous
#include <cuda_runtime.h>
#include <math.h>

typedef unsigned long long ull;
typedef unsigned int u32;

#define B_  2
#define L_  2048
#define S_  2048
#define D_  256
#define H_  8
#define SPLITS 2
#define SHALF (S_ / SPLITS)      // 1024
#define ST 16
#define NT (SHALF / ST)          // 64

// ---------------- f32x2 packed math ----------------
#define PACK2(d, x, y) asm("mov.b64 %0, {%1, %2};" : "=l"(d) : "r"(__float_as_uint(x)), "r"(__float_as_uint(y)))
#define UNPACK2(x, y, d) do { u32 _lo, _hi; \
    asm("mov.b64 {%0, %1}, %2;" : "=r"(_lo), "=r"(_hi) : "l"(d)); \
    (x) = __uint_as_float(_lo); (y) = __uint_as_float(_hi); } while (0)
#define FMA2(d, a, b, c) asm("fma.rn.f32x2 %0, %1, %2, %3;" : "=l"(d) : "l"(a), "l"(b), "l"(c))
#define MUL2(d, a, b)    asm("mul.rn.f32x2 %0, %1, %2;"     : "=l"(d) : "l"(a), "l"(b))
#define ADD2(d, a, b)    asm("add.rn.f32x2 %0, %1, %2;"     : "=l"(d) : "l"(a), "l"(b))

__device__ __forceinline__ float ex2f(float x) {
    float r;
    asm("ex2.approx.ftz.f32 %0, %1;" : "=f"(r) : "f"(x));
    return r;
}

// ---------------- scratch ----------------
__device__ float g_Q[(size_t)B_ * L_ * D_];
__device__ float g_K[(size_t)B_ * S_ * D_];
__device__ float g_V[(size_t)B_ * S_ * D_];
__device__ float g_OP[(size_t)SPLITS * B_ * L_ * D_];
__device__ float g_SS[(size_t)SPLITS * B_ * H_ * L_];
__device__ float g_O[(size_t)B_ * L_ * D_];
__device__ float g_M[(size_t)B_ * L_ * D_];
__device__ float g_HB[(size_t)B_ * L_ * 2 * D_];
__device__ float g_T[(size_t)B_ * L_ * D_];

// ---------------- GEMM: Y[M,N] = X[M,K] @ W[N,K]^T ----------------
// Tile 64x64, 128 threads, microtile 4(m)x8(n), f32x2 pairs along m.
// Double-buffered via register staging.
template <bool RELU, bool SPLIT>
__global__ void __launch_bounds__(128) gemm64(
    const float* __restrict__ X, const float* __restrict__ X2,
    const float* __restrict__ W, float* __restrict__ Y,
    int M, int N, int K) {
    __shared__ float XsT[16][68];   // [k][m]
    __shared__ float BsT[16][72];   // [k][n]
    const int bm = blockIdx.y * 64, bn = blockIdx.x * 64;
    const int t = threadIdx.x, tx = t & 7, ty = t >> 3;
    const int NTk = K >> 4;

    float4 xr[2], wr[2];
    #pragma unroll
    for (int i = 0; i < 2; i++) {   // prologue load k-tile 0
        int idx = t + 128 * i; int r = idx >> 2; int c = (idx & 3) * 4;
        if (SPLIT) xr[i] = (c < 256) ? *(const float4*)(X + (size_t)(bm + r) * 256 + c)
                                     : *(const float4*)(X2 + (size_t)(bm + r) * 256 + (c - 256));
        else       xr[i] = *(const float4*)(X + (size_t)(bm + r) * K + c);
        wr[i] = *(const float4*)(W + (size_t)(bn + r) * K + c);
    }

    ull acc[2][8]; ull zero; PACK2(zero, 0.0f, 0.0f);
    #pragma unroll
    for (int p = 0; p < 2; p++)
        #pragma unroll
        for (int n = 0; n < 8; n++) acc[p][n] = zero;

    for (int kt = 0; kt < NTk; kt++) {
        __syncthreads();
        #pragma unroll
        for (int i = 0; i < 2; i++) {
            int idx = t + 128 * i; int r = idx >> 2; int c = (idx & 3) * 4;
            XsT[c + 0][r] = xr[i].x; XsT[c + 1][r] = xr[i].y;
            XsT[c + 2][r] = xr[i].z; XsT[c + 3][r] = xr[i].w;
            BsT[c + 0][r] = wr[i].x; BsT[c + 1][r] = wr[i].y;
            BsT[c + 2][r] = wr[i].z; BsT[c + 3][r] = wr[i].w;
        }
        if (kt + 1 < NTk) {
            int k0 = (kt + 1) * 16;
            #pragma unroll
            for (int i = 0; i < 2; i++) {
                int idx = t + 128 * i; int r = idx >> 2; int c = (idx & 3) * 4;
                int kc = k0 + c;
                if (SPLIT) xr[i] = (kc < 256) ? *(const float4*)(X + (size_t)(bm + r) * 256 + kc)
                                              : *(const float4*)(X2 + (size_t)(bm + r) * 256 + (kc - 256));
                else       xr[i] = *(const float4*)(X + (size_t)(bm + r) * K + kc);
                wr[i] = *(const float4*)(W + (size_t)(bn + r) * K + kc);
            }
        }
        __syncthreads();
        #pragma unroll
        for (int kk = 0; kk < 16; kk++) {
            ulonglong2 a = *(const ulonglong2*)&XsT[kk][ty * 4];
            float4 b0 = *(const float4*)&BsT[kk][tx * 8];
            float4 b1 = *(const float4*)&BsT[kk][tx * 8 + 4];
            ull bb;
            PACK2(bb, b0.x, b0.x); FMA2(acc[0][0], a.x, bb, acc[0][0]); FMA2(acc[1][0], a.y, bb, acc[1][0]);
            PACK2(bb, b0.y, b0.y); FMA2(acc[0][1], a.x, bb, acc[0][1]); FMA2(acc[1][1], a.y, bb, acc[1][1]);
            PACK2(bb, b0.z, b0.z); FMA2(acc[0][2], a.x, bb, acc[0][2]); FMA2(acc[1][2], a.y, bb, acc[1][2]);
            PACK2(bb, b0.w, b0.w); FMA2(acc[0][3], a.x, bb, acc[0][3]); FMA2(acc[1][3], a.y, bb, acc[1][3]);
            PACK2(bb, b1.x, b1.x); FMA2(acc[0][4], a.x, bb, acc[0][4]); FMA2(acc[1][4], a.y, bb, acc[1][4]);
            PACK2(bb, b1.y, b1.y); FMA2(acc[0][5], a.x, bb, acc[0][5]); FMA2(acc[1][5], a.y, bb, acc[1][5]);
            PACK2(bb, b1.z, b1.z); FMA2(acc[0][6], a.x, bb, acc[0][6]); FMA2(acc[1][6], a.y, bb, acc[1][6]);
            PACK2(bb, b1.w, b1.w); FMA2(acc[0][7], a.x, bb, acc[0][7]); FMA2(acc[1][7], a.y, bb, acc[1][7]);
        }
    }

    float o[4][8];
    #pragma unroll
    for (int n = 0; n < 8; n++) {
        UNPACK2(o[0][n], o[1][n], acc[0][n]);
        UNPACK2(o[2][n], o[3][n], acc[1][n]);
    }
    #pragma unroll
    for (int r = 0; r < 4; r++) {
        if (RELU)
            #pragma unroll
            for (int n = 0; n < 8; n++) o[r][n] = fmaxf(o[r][n], 0.0f);
        float4 w0, w1;
        w0.x = o[r][0]; w0.y = o[r][1]; w0.z = o[r][2]; w0.w = o[r][3];
        w1.x = o[r][4]; w1.y = o[r][5]; w1.z = o[r][6]; w1.w = o[r][7];
        float* yp = Y + (size_t)(bm + ty * 4 + r) * N + bn + tx * 8;
        *(float4*)yp = w0;
        *(float4*)(yp + 4) = w1;
    }
}

// ---------------- fused attention, no-max softmax, S-split ----------------
// Block: 256 threads = 8 warps (warp = head), lane = l-row. 32 l-rows/block.
// Grid: (L/32, SPLITS, B). Double-buffered K/V tiles (ST=16) via cp.async.
// smem: Ks[2][16][256] | Vs[2][16][256] | Afs[2][32][17]  = 69888 bytes.
#define ATTN_SMEM 69888

#define ISSUE_KV(t_, buf_) do { \
    const float* ksrc_ = Kb + (size_t)(sbase + (t_) * ST) * D_; \
    const float* vsrc_ = Vb + (size_t)(sbase + (t_) * ST) * D_; \
    u32 kd_ = kbase + (u32)(buf_) * 16384; \
    u32 vd_ = vbase + (u32)(buf_) * 16384; \
    _Pragma("unroll") \
    for (int i_ = 0; i_ < 4; i_++) { \
        int idx_ = tid + 256 * i_; int s_ = idx_ >> 6; int c_ = (idx_ & 63) * 4; \
        asm volatile("cp.async.cg.shared.global [%0], [%1], 16;" :: \
            "r"(kd_ + (u32)(s_ * 256 + c_) * 4), "l"(ksrc_ + s_ * 256 + c_)); \
        asm volatile("cp.async.cg.shared.global [%0], [%1], 16;" :: \
            "r"(vd_ + (u32)(s_ * 256 + c_) * 4), "l"(vsrc_ + s_ * 256 + c_)); \
    } \
    asm volatile("cp.async.commit_group;"); \
} while (0)

#define LOAD_AF(t_) do { \
    afr0 = afb[(size_t)(tid >> 4) * S_ + (t_) * ST + (tid & 15)]; \
    afr1 = afb[(size_t)((tid >> 4) + 16) * S_ + (t_) * ST + (tid & 15)]; \
} while (0)

#define STORE_AF(buf_) do { \
    Afs[(buf_) * 544 + (tid >> 4) * 17 + (tid & 15)] = afr0; \
    Afs[(buf_) * 544 + ((tid >> 4) + 16) * 17 + (tid & 15)] = afr1; \
} while (0)

__global__ void __launch_bounds__(256, 2) attn2(
    const float* __restrict__ Qg, const float* __restrict__ Kg,
    const float* __restrict__ Vg, const float* __restrict__ af,
    float* __restrict__ Op, float* __restrict__ SSp) {
    extern __shared__ float sm[];
    float* Ksm = sm;                 // 2*16*256 = 8192 floats
    float* Vsm = sm + 8192;          // 8192
    float* Afs = sm + 16384;         // 2*32*17 = 1088

    const int b = blockIdx.z, sp = blockIdx.y;
    const int l0 = blockIdx.x * 32;
    const int tid = threadIdx.x;
    const int w = tid >> 5, lane = tid & 31;
    const int sbase = sp * SHALF;
    const float* Kb  = Kg + (size_t)b * S_ * D_;
    const float* Vb  = Vg + (size_t)b * S_ * D_;
    const float* afb = af + ((size_t)b * L_ + l0) * S_ + sbase;
    const u32 smb = (u32)__cvta_generic_to_shared(sm);
    const u32 kbase = smb;
    const u32 vbase = smb + 8192 * 4;

    // q regs: 32 dims pre-scaled by log2(e)/sqrt(32), packed in pairs
    ull q[16];
    {
        const float QS = 0.25503486f;  // 1.4426950408889634 / sqrt(32)
        const float* qr = Qg + ((size_t)b * L_ + l0 + lane) * D_ + w * 32;
        #pragma unroll
        for (int i = 0; i < 8; i++) {
            float4 f = *(const float4*)(qr + i * 4);
            f.x *= QS; f.y *= QS; f.z *= QS; f.w *= QS;
            PACK2(q[2 * i], f.x, f.y);
            PACK2(q[2 * i + 1], f.z, f.w);
        }
    }
    ull zero; PACK2(zero, 0.0f, 0.0f);
    ull o[16];
    #pragma unroll
    for (int i = 0; i < 16; i++) o[i] = zero;
    float ssum = 0.0f;
    float afr0, afr1;

    // prologue
    ISSUE_KV(0, 0);
    LOAD_AF(0);
    ISSUE_KV(1, 1);
    STORE_AF(0);
    LOAD_AF(1);

    for (int t = 0; t < NT; t++) {
        const int buf = t & 1;
        if (t + 1 < NT) asm volatile("cp.async.wait_group 1;");
        else            asm volatile("cp.async.wait_group 0;");
        __syncthreads();
        if (t + 1 < NT) STORE_AF(buf ^ 1);
        if (t + 2 < NT) LOAD_AF(t + 2);

        const float* ks  = Ksm + buf * 4096 + w * 32;
        const float* vs  = Vsm + buf * 4096 + w * 32;
        const float* afl = Afs + buf * 544 + lane * 17;

        #pragma unroll 4
        for (int s = 0; s < ST; s++) {
            const ulonglong2* kp = (const ulonglong2*)(ks + s * 256);
            ull a0, a1, a2, a3;
            {
                ulonglong2 k0v = kp[0], k1v = kp[1];
                MUL2(a0, q[0], k0v.x); MUL2(a1, q[1], k0v.y);
                MUL2(a2, q[2], k1v.x); MUL2(a3, q[3], k1v.y);
            }
            { ulonglong2 kv = kp[2]; FMA2(a0, q[4],  kv.x, a0); FMA2(a1, q[5],  kv.y, a1); }
            { ulonglong2 kv = kp[3]; FMA2(a2, q[6],  kv.x, a2); FMA2(a3, q[7],  kv.y, a3); }
            { ulonglong2 kv = kp[4]; FMA2(a0, q[8],  kv.x, a0); FMA2(a1, q[9],  kv.y, a1); }
            { ulonglong2 kv = kp[5]; FMA2(a2, q[10], kv.x, a2); FMA2(a3, q[11], kv.y, a3); }
            { ulonglong2 kv = kp[6]; FMA2(a0, q[12], kv.x, a0); FMA2(a1, q[13], kv.y, a1); }
            { ulonglong2 kv = kp[7]; FMA2(a2, q[14], kv.x, a2); FMA2(a3, q[15], kv.y, a3); }
            ADD2(a0, a0, a1); ADD2(a2, a2, a3); ADD2(a0, a0, a2);
            float x0, x1; UNPACK2(x0, x1, a0);
            float p = ex2f((x0 + x1) * afl[s]);
            ssum += p;
            ull pp; PACK2(pp, p, p);
            const ulonglong2* vp = (const ulonglong2*)(vs + s * 256);
            #pragma unroll
            for (int j = 0; j < 8; j++) {
                ulonglong2 vv = vp[j];
                FMA2(o[2 * j],     pp, vv.x, o[2 * j]);
                FMA2(o[2 * j + 1], pp, vv.y, o[2 * j + 1]);
            }
        }
        __syncthreads();
        if (t + 2 < NT) ISSUE_KV(t + 2, buf);
    }

    // write raw partials (division happens in combine)
    float* op = Op + (((size_t)sp * B_ + b) * L_ + l0 + lane) * D_ + w * 32;
    #pragma unroll
    for (int j = 0; j < 8; j++) {
        float v0, v1, v2, v3;
        UNPACK2(v0, v1, o[2 * j]);
        UNPACK2(v2, v3, o[2 * j + 1]);
        float4 f; f.x = v0; f.y = v1; f.z = v2; f.w = v3;
        *(float4*)(op + j * 4) = f;
    }
    SSp[(((size_t)sp * B_ + b) * H_ + w) * L_ + l0 + lane] = ssum;
}

// ---------------- combine split partials: O = (O0+O1)/(s0+s1) ----------------
__global__ void combine_kernel(const float* __restrict__ Op, const float* __restrict__ SSp,
                               float* __restrict__ O) {
    size_t i = (size_t)blockIdx.x * 256 + threadIdx.x;   // per float4
    size_t e = i * 4;
    int d = (int)(e & 255);
    size_t bl = e >> 8;                 // b*L + l
    int h = d >> 5;
    size_t b = bl >> 11, l = bl & 2047;
    float4 a = *(const float4*)(Op + e);
    float4 c = *(const float4*)(Op + (size_t)B_ * L_ * D_ + e);
    float s = SSp[(b * H_ + h) * L_ + l] + SSp[((size_t)B_ * H_ + b * H_ + h) * L_ + l];
    float inv = 1.0f / s;
    float4 r;
    r.x = (a.x + c.x) * inv; r.y = (a.y + c.y) * inv;
    r.z = (a.z + c.z) * inv; r.w = (a.w + c.w) * inv;
    *(float4*)(O + e) = r;
}

// ---------------- LayerNorm over D=256 ----------------
template <bool RESID>
__global__ void ln_kernel(const float* __restrict__ in, const float* __restrict__ g,
                          const float* __restrict__ bt, const float* __restrict__ resid,
                          float* __restrict__ out) {
    const size_t row = blockIdx.x;
    const int tid = threadIdx.x;
    float x = in[row * D_ + tid];
    __shared__ float red[256];
    red[tid] = x; __syncthreads();
    #pragma unroll
    for (int off = 128; off > 0; off >>= 1) {
        if (tid < off) red[tid] += red[tid + off];
        __syncthreads();
    }
    const float mean = red[0] * (1.0f / D_);
    __syncthreads();
    const float d = x - mean;
    red[tid] = d * d; __syncthreads();
    #pragma unroll
    for (int off = 128; off > 0; off >>= 1) {
        if (tid < off) red[tid] += red[tid + off];
        __syncthreads();
    }
    const float var = red[0] * (1.0f / D_);
    float y = d * rsqrtf(var + 1e-5f) * g[tid] + bt[tid];
    if (RESID) y += resid[row * D_ + tid];
    out[row * D_ + tid] = y;
}

// ---------------- launch ----------------
extern "C" void kernel_launch(void* const* d_in, const int* in_sizes, int n_in,
                              void* d_out, int out_size) {
    const float* x   = (const float*)d_in[0];
    const float* src = (const float*)d_in[1];
    const float* af  = (const float*)d_in[2];
    const float* Wq  = (const float*)d_in[3];
    const float* Wk  = (const float*)d_in[4];
    const float* Wv  = (const float*)d_in[5];
    const float* Wm  = (const float*)d_in[6];
    const float* W1  = (const float*)d_in[7];
    const float* W2  = (const float*)d_in[8];
    const float* g1  = (const float*)d_in[9];
    const float* b1  = (const float*)d_in[10];
    const float* g2  = (const float*)d_in[11];
    const float* b2  = (const float*)d_in[12];
    float* out = (float*)d_out;

    float *Q, *K, *V, *OP, *SS, *O, *M, *HB, *T;
    cudaGetSymbolAddress((void**)&Q,  g_Q);
    cudaGetSymbolAddress((void**)&K,  g_K);
    cudaGetSymbolAddress((void**)&V,  g_V);
    cudaGetSymbolAddress((void**)&OP, g_OP);
    cudaGetSymbolAddress((void**)&SS, g_SS);
    cudaGetSymbolAddress((void**)&O,  g_O);
    cudaGetSymbolAddress((void**)&M,  g_M);
    cudaGetSymbolAddress((void**)&HB, g_HB);
    cudaGetSymbolAddress((void**)&T,  g_T);

    cudaFuncSetAttribute(attn2, cudaFuncAttributeMaxDynamicSharedMemorySize, ATTN_SMEM);

    const int ML = B_ * L_;  // 4096

    // projections
    gemm64<false, false><<<dim3(4, ML / 64), 128>>>(x,   nullptr, Wq, Q, ML, 256, 256);
    gemm64<false, false><<<dim3(4, ML / 64), 128>>>(src, nullptr, Wk, K, ML, 256, 256);
    gemm64<false, false><<<dim3(4, ML / 64), 128>>>(src, nullptr, Wv, V, ML, 256, 256);

    // attention
    attn2<<<dim3(L_ / 32, SPLITS, B_), 256, ATTN_SMEM>>>(Q, K, V, af, OP, SS);
    combine_kernel<<<(B_ * L_ * D_ / 4) / 256, 256>>>(OP, SS, O);

    // output proj + LN1
    gemm64<false, false><<<dim3(4, ML / 64), 128>>>(O, nullptr, Wm, M, ML, 256, 256);
    ln_kernel<false><<<ML, 256>>>(M, g1, b1, nullptr, M);

    // MLP
    gemm64<true, true><<<dim3(8, ML / 64), 128>>>(x, M, W1, HB, ML, 512, 512);
    gemm64<false, false><<<dim3(4, ML / 64), 128>>>(HB, nullptr, W2, T, ML, 256, 512);

    // LN2 + residual -> out
    ln_kernel<true><<<ML, 256>>>(T, g2, b2, x, out);
}